// round 7
// baseline (speedup 1.0000x reference)
#include <cuda_runtime.h>
#include <math.h>

#define NPRE   1024
#define NPOST  256
#define MAXB   128

// scan kernel geometry: warp owns 4 neurons x 8 k-slices
#define CH     64                 // k-chunk length
#define NSUB   8                  // slices per chunk
#define KSUB   (CH / NSUB)        // 8 k per slice
#define NTHR   512                // 16 warps -> 64 neurons per block
#define NT     64
#define NGRP   (NPOST / NT)       // 4 neuron groups per batch
#define NCHUNK (NPRE / CH)        // 16 chunks
#define FULL   0xffffffffu

#define INV_E_F  0.36787944117144233f
#define E_F      2.718281828459045f

// Scratch: packed per-k metadata (s, e^s, s*e^s, idx-bits), one row per batch.
__device__ float4 g_m4[MAXB * NPRE];

// ---------------------------------------------------------------------------
// Kernel 1: stable ascending sort of each batch row (matches jnp.argsort).
// (verified since R4) Now emits packed float4 metadata directly.
// ---------------------------------------------------------------------------
__global__ void __launch_bounds__(512) sort_kernel(const float* __restrict__ spikes)
{
    __shared__ unsigned long long keys[NPRE];
    const int b   = blockIdx.x;
    const int tid = threadIdx.x;

    for (int i = tid; i < NPRE; i += 512) {
        float v = spikes[b * NPRE + i];
        unsigned int bits = __float_as_uint(v);
        bits = (bits & 0x80000000u) ? ~bits : (bits | 0x80000000u);
        keys[i] = ((unsigned long long)bits << 32) | (unsigned int)i;
    }
    __syncthreads();

    for (int k = 2; k <= NPRE; k <<= 1) {
        for (int j = k >> 1; j >= 32; j >>= 1) {
            #pragma unroll
            for (int rep = 0; rep < NPRE / 512; ++rep) {
                int i = tid + rep * 512;
                int ixj = i ^ j;
                if (ixj > i) {
                    unsigned long long A = keys[i];
                    unsigned long long C = keys[ixj];
                    bool up = ((i & k) == 0);
                    if ((A > C) == up) { keys[i] = C; keys[ixj] = A; }
                }
            }
            __syncthreads();
        }
        unsigned long long v0 = keys[tid];
        unsigned long long v1 = keys[tid + 512];
        const bool up0 = ((tid & k) == 0);
        const bool up1 = (((tid + 512) & k) == 0);
        #pragma unroll
        for (int j = 16; j >= 1; j >>= 1) {
            if (j < k) {
                bool lower = ((tid & j) == 0);
                unsigned long long p0 = __shfl_xor_sync(FULL, v0, j);
                unsigned long long p1 = __shfl_xor_sync(FULL, v1, j);
                bool km0 = (lower == up0);
                bool km1 = (lower == up1);
                unsigned long long mn0 = (v0 < p0) ? v0 : p0;
                unsigned long long mx0 = (v0 < p0) ? p0 : v0;
                unsigned long long mn1 = (v1 < p1) ? v1 : p1;
                unsigned long long mx1 = (v1 < p1) ? p1 : v1;
                v0 = km0 ? mn0 : mx0;
                v1 = km1 ? mn1 : mx1;
            }
        }
        keys[tid]       = v0;
        keys[tid + 512] = v1;
        __syncthreads();
    }

    for (int i = tid; i < NPRE; i += 512) {
        unsigned long long kk = keys[i];
        unsigned int hi = (unsigned int)(kk >> 32);
        unsigned int bits = (hi & 0x80000000u) ? (hi ^ 0x80000000u) : ~hi;
        float s = __uint_as_float(bits);
        float e = expf(s);
        g_m4[b * NPRE + i] =
            make_float4(s, e, s * e, __int_as_float((int)(kk & 0xFFFFFFFFu)));
    }
}

// ---------------------------------------------------------------------------
// Lambert W0 on [-1/e, 0): same clip/init/Halley form as the reference.
// ---------------------------------------------------------------------------
__device__ __forceinline__ float lambertw0_dev(float z)
{
    float zc = fminf(fmaxf(z, -INV_E_F + 1e-8f), -1e-30f);
    float w;
    if (zc < -0.2f)
        w = -1.0f + sqrtf(2.0f * fmaf(E_F, zc, 1.0f));
    else
        w = zc * (1.0f - zc);
    #pragma unroll
    for (int it = 0; it < 6; ++it) {
        float ew  = __expf(w);
        float f   = fmaf(w, ew, -zc);
        float wp1 = w + 1.0f;
        float denom = fmaf(2.0f * ew * wp1, wp1, -(w + 2.0f) * f);
        w = w - __fdividef(f * 2.0f * wp1, denom);
    }
    return w;
}

// ---------------------------------------------------------------------------
// Kernel 2: warp-autonomous chunked causal scan w/ per-lane concavity prune.
//   Single __syncthreads after metadata staging; main loop barrier-free.
//   Warp layout: lane = q*4 + nl -> 8 slices x 4 neurons. Per chunk:
//     - slice totals (pa,pb): 8 x (LDS.128 + 2 FMA)
//     - segmented shfl scan -> exclusive prefix + chunk totals
//     - SOUND slice prune (verified in R4): gate a_k*s_{k+1}-b_k >= e^{s_{k+1}}
//       is bounded by concave H(s)=a_hi*s-b_lo-e^s (a monotone up, b monotone
//       up, w>=0), max at clamp(ln a_hi, s_lo, s_hi); max < -1e-2 => no
//       candidate in slice. Final slice of final chunk force-flagged (the
//       s_next=inf last-row exemption always passes the gate).
//     - flagged slices only: exact pipelined gate scan + Lambert (rare),
//       first valid == min (w >= 0 => monotone causal crossing).
//     - ballot/ffs/shfl min-k resolution; warp exits when its 4 neurons done.
// ---------------------------------------------------------------------------
__global__ void __launch_bounds__(NTHR) scan_kernel(const float* __restrict__ Wmat,
                                                    float* __restrict__ out)
{
    __shared__ float4 sh_m[NPRE + 1];

    const int b    = blockIdx.x / NGRP;
    const int grp  = blockIdx.x % NGRP;
    const int tid  = threadIdx.x;
    const int wrp  = tid >> 5;
    const int l    = tid & 31;
    const int q    = l >> 2;            // slice 0..7
    const int nl   = l & 3;             // neuron-in-warp 0..3
    const int ng   = grp * NT + wrp * 4 + nl;   // global output neuron
    const int base = b * NPRE;

    // ---- stage packed metadata once ----
    for (int i = tid; i < NPRE; i += NTHR)
        sh_m[i] = g_m4[base + i];
    if (tid == 0) sh_m[NPRE] = make_float4(INFINITY, INFINITY, 0.0f, 0.0f);
    __syncthreads();

    // ---- prologue: chunk-0 weights ----
    float wv[KSUB];
    #pragma unroll
    for (int kk = 0; kk < KSUB; ++kk) {
        int row = __float_as_int(sh_m[q * KSUB + kk].w);
        wv[kk] = __ldg(&Wmat[row * NPOST + ng]);
    }

    bool  done  = false;
    float a_run = 0.0f, b_run = 0.0f;

    for (int c = 0; c < NCHUNK; ++c) {
        const int kbase = c * CH + q * KSUB;

        // ---- slice totals ----
        float pa = 0.0f, pb = 0.0f;
        if (!done) {
            #pragma unroll
            for (int kk = 0; kk < KSUB; ++kk) {
                float4 m = sh_m[kbase + kk];
                pa = fmaf(wv[kk], m.y, pa);
                pb = fmaf(wv[kk], m.z, pb);
            }
        }
        // ---- prefetch next chunk weights (overlaps scan/prune latency) ----
        float wn[KSUB];
        if (!done && c + 1 < NCHUNK) {
            #pragma unroll
            for (int kk = 0; kk < KSUB; ++kk) {
                int row = __float_as_int(sh_m[(c + 1) * CH + q * KSUB + kk].w);
                wn[kk] = __ldg(&Wmat[row * NPOST + ng]);
            }
        }

        // ---- segmented inclusive scan over q (stride-4 lanes) ----
        float ia = pa, ib = pb, t0, t1;
        t0 = __shfl_up_sync(FULL, ia, 4);  t1 = __shfl_up_sync(FULL, ib, 4);
        if (q >= 1) { ia += t0; ib += t1; }
        t0 = __shfl_up_sync(FULL, ia, 8);  t1 = __shfl_up_sync(FULL, ib, 8);
        if (q >= 2) { ia += t0; ib += t1; }
        t0 = __shfl_up_sync(FULL, ia, 16); t1 = __shfl_up_sync(FULL, ib, 16);
        if (q >= 4) { ia += t0; ib += t1; }
        float ea = __shfl_up_sync(FULL, ia, 4);   // exclusive prefix
        float eb = __shfl_up_sync(FULL, ib, 4);
        if (q == 0) { ea = 0.0f; eb = 0.0f; }
        float tot_a = __shfl_sync(FULL, ia, 28 + nl);
        float tot_b = __shfl_sync(FULL, ib, 28 + nl);

        // ---- sound concavity prune (per lane) ----
        bool flag = false;
        if (!done) {
            float a_hi = a_run + ea + pa;       // slice-inclusive max of a_k
            float b_lo = b_run + eb;            // slice-start min of b_k
            float2 mlo = *(const float2*)&sh_m[kbase + 1];      // (s, e)
            float2 mhi = *(const float2*)&sh_m[kbase + KSUB];
            float la = __logf(a_hi);
            float m;
            if (la <= mlo.x)      m = fmaf(a_hi, mlo.x, -b_lo) - mlo.y;
            else if (la >= mhi.x) m = fmaf(a_hi, mhi.x, -b_lo) - mhi.y;
            else                  m = fmaf(a_hi, la - 1.0f, -b_lo);  // e^la==a_hi
            flag = (m >= -1e-2f);
            if (c == NCHUNK - 1 && q == NSUB - 1) flag = true;  // last-row exemption
        }

        // ---- exact gate scan, only on flagged slices (rare) ----
        bool  found = false;
        float ct    = INFINITY;
        if (flag) {
            float aa = a_run + ea;
            float bb = b_run + eb;
            float4 mc = sh_m[kbase];
            #pragma unroll
            for (int kk = 0; kk < KSUB; ++kk) {
                if (!found) {
                    aa = fmaf(wv[kk], mc.y, aa);
                    bb = fmaf(wv[kk], mc.z, bb);
                    float4 mn = sh_m[kbase + kk + 1];
                    // exact gate: z >= -1/e AND t <= s_next
                    if (fmaf(aa, mn.x, -bb) >= mn.y) {
                        float r = __fdividef(bb, aa);
                        float z = -__fdividef(__expf(r), aa);
                        bool valid = (aa > 0.0f) && (z >= -INV_E_F);
                        float t = r - lambertw0_dev(z);
                        if (valid && t >= mc.x) {    // causal lower bound
                            found = true; ct = t;    // first valid in slice
                        }
                    }
                    mc = mn;
                }
            }
        }

        // ---- per-neuron resolution: lowest-q found lane wins (min k) ----
        unsigned bal = __ballot_sync(FULL, found);
        unsigned gb  = bal & (0x11111111u << nl);
        int src = gb ? (int)(__ffs(gb) - 1) : l;
        float tw = __shfl_sync(FULL, ct, src);
        if (!done) {
            if (gb) {
                done = true;
                if (q == 0) out[b * NPOST + ng] = tw;
            } else {
                a_run += tot_a;
                b_run += tot_b;
            }
        }

        if (__all_sync(FULL, done)) break;   // warp-local early exit

        #pragma unroll
        for (int kk = 0; kk < KSUB; ++kk) wv[kk] = wn[kk];
    }

    if (!done && q == 0) out[b * NPOST + ng] = INFINITY;
}

// ---------------------------------------------------------------------------
extern "C" void kernel_launch(void* const* d_in, const int* in_sizes, int n_in,
                              void* d_out, int out_size)
{
    const float* spikes  = (const float*)d_in[0];
    const float* weights = (const float*)d_in[1];
    int sz = in_sizes[0];
    if (n_in >= 2 && in_sizes[0] > in_sizes[1]) {   // robustness to input order
        const float* t = spikes; spikes = weights; weights = t;
        sz = in_sizes[1];
    }
    int B = sz / NPRE;
    sort_kernel<<<B, 512>>>(spikes);
    scan_kernel<<<B * NGRP, NTHR>>>(weights, (float*)d_out);
}

// round 8
// speedup vs baseline: 1.4705x; 1.4705x over previous
#include <cuda_runtime.h>
#include <math.h>

#define NPRE   1024
#define NPOST  256
#define MAXB   128

// scan kernel geometry: warp owns 4 neurons x 8 k-slices
#define CH     64                 // k-chunk length
#define NSUB   8                  // slices per chunk
#define KSUB   (CH / NSUB)        // 8 k per slice
#define NTHR   512                // 16 warps -> 64 neurons per block
#define NT     64
#define NGRP   (NPOST / NT)       // 4 neuron groups per batch
#define NCHUNK (NPRE / CH)        // 16 chunks
#define FULL   0xffffffffu

// bank-conflict-free float4 indexing: lanes access i = c*64 + q*8 + kk;
// XOR the low 3 bits with q so the 8 q-groups land in 8 distinct 16B columns.
#define SWZ(i) ((i) ^ (((i) >> 3) & 7))

#define INV_E_F  0.36787944117144233f
#define E_F      2.718281828459045f

// Scratch: packed per-k metadata (s, e^s, s*e^s, idx-bits), one row per batch.
__device__ float4 g_m4[MAXB * NPRE];

// ---------------------------------------------------------------------------
// Kernel 1: stable ascending sort of each batch row (matches jnp.argsort).
// (verified since R4) Emits packed float4 metadata.
// ---------------------------------------------------------------------------
__global__ void __launch_bounds__(512) sort_kernel(const float* __restrict__ spikes)
{
    __shared__ unsigned long long keys[NPRE];
    const int b   = blockIdx.x;
    const int tid = threadIdx.x;

    for (int i = tid; i < NPRE; i += 512) {
        float v = spikes[b * NPRE + i];
        unsigned int bits = __float_as_uint(v);
        bits = (bits & 0x80000000u) ? ~bits : (bits | 0x80000000u);
        keys[i] = ((unsigned long long)bits << 32) | (unsigned int)i;
    }
    __syncthreads();

    for (int k = 2; k <= NPRE; k <<= 1) {
        for (int j = k >> 1; j >= 32; j >>= 1) {
            #pragma unroll
            for (int rep = 0; rep < NPRE / 512; ++rep) {
                int i = tid + rep * 512;
                int ixj = i ^ j;
                if (ixj > i) {
                    unsigned long long A = keys[i];
                    unsigned long long C = keys[ixj];
                    bool up = ((i & k) == 0);
                    if ((A > C) == up) { keys[i] = C; keys[ixj] = A; }
                }
            }
            __syncthreads();
        }
        unsigned long long v0 = keys[tid];
        unsigned long long v1 = keys[tid + 512];
        const bool up0 = ((tid & k) == 0);
        const bool up1 = (((tid + 512) & k) == 0);
        #pragma unroll
        for (int j = 16; j >= 1; j >>= 1) {
            if (j < k) {
                bool lower = ((tid & j) == 0);
                unsigned long long p0 = __shfl_xor_sync(FULL, v0, j);
                unsigned long long p1 = __shfl_xor_sync(FULL, v1, j);
                bool km0 = (lower == up0);
                bool km1 = (lower == up1);
                unsigned long long mn0 = (v0 < p0) ? v0 : p0;
                unsigned long long mx0 = (v0 < p0) ? p0 : v0;
                unsigned long long mn1 = (v1 < p1) ? v1 : p1;
                unsigned long long mx1 = (v1 < p1) ? p1 : v1;
                v0 = km0 ? mn0 : mx0;
                v1 = km1 ? mn1 : mx1;
            }
        }
        keys[tid]       = v0;
        keys[tid + 512] = v1;
        __syncthreads();
    }

    for (int i = tid; i < NPRE; i += 512) {
        unsigned long long kk = keys[i];
        unsigned int hi = (unsigned int)(kk >> 32);
        unsigned int bits = (hi & 0x80000000u) ? (hi ^ 0x80000000u) : ~hi;
        float s = __uint_as_float(bits);
        float e = expf(s);
        g_m4[b * NPRE + i] =
            make_float4(s, e, s * e, __int_as_float((int)(kk & 0xFFFFFFFFu)));
    }
}

// ---------------------------------------------------------------------------
// Lambert W0 on [-1/e, 0): same clip/init/Halley form as the reference.
// ---------------------------------------------------------------------------
__device__ __forceinline__ float lambertw0_dev(float z)
{
    float zc = fminf(fmaxf(z, -INV_E_F + 1e-8f), -1e-30f);
    float w;
    if (zc < -0.2f)
        w = -1.0f + sqrtf(2.0f * fmaf(E_F, zc, 1.0f));
    else
        w = zc * (1.0f - zc);
    #pragma unroll
    for (int it = 0; it < 6; ++it) {
        float ew  = __expf(w);
        float f   = fmaf(w, ew, -zc);
        float wp1 = w + 1.0f;
        float denom = fmaf(2.0f * ew * wp1, wp1, -(w + 2.0f) * f);
        w = w - __fdividef(f * 2.0f * wp1, denom);
    }
    return w;
}

// ---------------------------------------------------------------------------
// Kernel 2: warp-autonomous chunked causal scan, swizzled metadata,
// per-lane concavity prune. Single __syncthreads; main loop barrier-free.
// (structure verified R6/R7; swizzle fixes R7's 8-way bank conflicts)
// ---------------------------------------------------------------------------
__global__ void __launch_bounds__(NTHR) scan_kernel(const float* __restrict__ Wmat,
                                                    float* __restrict__ out)
{
    __shared__ float4 sh_m[NPRE + 1];

    const int b    = blockIdx.x / NGRP;
    const int grp  = blockIdx.x % NGRP;
    const int tid  = threadIdx.x;
    const int wrp  = tid >> 5;
    const int l    = tid & 31;
    const int q    = l >> 2;            // slice 0..7
    const int nl   = l & 3;             // neuron-in-warp 0..3
    const int ng   = grp * NT + wrp * 4 + nl;   // global output neuron
    const int base = b * NPRE;

    // ---- stage packed metadata once (swizzled) ----
    for (int i = tid; i < NPRE; i += NTHR)
        sh_m[SWZ(i)] = g_m4[base + i];
    if (tid == 0) sh_m[NPRE] = make_float4(INFINITY, INFINITY, 0.0f, 0.0f);
    __syncthreads();

    // ---- prologue: chunk-0 weights ----
    float wv[KSUB];
    #pragma unroll
    for (int kk = 0; kk < KSUB; ++kk) {
        int row = __float_as_int(sh_m[SWZ(q * KSUB + kk)].w);
        wv[kk] = __ldg(&Wmat[row * NPOST + ng]);
    }

    bool  done  = false;
    float a_run = 0.0f, b_run = 0.0f;

    for (int c = 0; c < NCHUNK; ++c) {
        const int kbase = c * CH + q * KSUB;

        // ---- slice totals (conflict-free LDS.128) ----
        float pa = 0.0f, pb = 0.0f;
        if (!done) {
            #pragma unroll
            for (int kk = 0; kk < KSUB; ++kk) {
                float4 m = sh_m[SWZ(kbase + kk)];
                pa = fmaf(wv[kk], m.y, pa);
                pb = fmaf(wv[kk], m.z, pb);
            }
        }
        // ---- prefetch next chunk weights (overlaps scan/prune latency) ----
        float wn[KSUB];
        if (!done && c + 1 < NCHUNK) {
            #pragma unroll
            for (int kk = 0; kk < KSUB; ++kk) {
                int row = __float_as_int(sh_m[SWZ((c + 1) * CH + q * KSUB + kk)].w);
                wn[kk] = __ldg(&Wmat[row * NPOST + ng]);
            }
        }

        // ---- segmented inclusive scan over q (stride-4 lanes) ----
        float ia = pa, ib = pb, t0, t1;
        t0 = __shfl_up_sync(FULL, ia, 4);  t1 = __shfl_up_sync(FULL, ib, 4);
        if (q >= 1) { ia += t0; ib += t1; }
        t0 = __shfl_up_sync(FULL, ia, 8);  t1 = __shfl_up_sync(FULL, ib, 8);
        if (q >= 2) { ia += t0; ib += t1; }
        t0 = __shfl_up_sync(FULL, ia, 16); t1 = __shfl_up_sync(FULL, ib, 16);
        if (q >= 4) { ia += t0; ib += t1; }
        float ea = __shfl_up_sync(FULL, ia, 4);   // exclusive prefix
        float eb = __shfl_up_sync(FULL, ib, 4);
        if (q == 0) { ea = 0.0f; eb = 0.0f; }
        float tot_a = __shfl_sync(FULL, ia, 28 + nl);
        float tot_b = __shfl_sync(FULL, ib, 28 + nl);

        // ---- sound concavity prune (per lane; verified R4/R7) ----
        // gate a_k*s_{k+1}-b_k >= e^{s_{k+1}} bounded by concave
        // H(s)=a_hi*s-b_lo-e^s, max at clamp(ln a_hi, s_lo, s_hi).
        bool flag = false;
        if (!done) {
            float a_hi = a_run + ea + pa;       // slice-inclusive max of a_k
            float b_lo = b_run + eb;            // slice-start min of b_k
            float4 m1 = sh_m[SWZ(kbase + 1)];
            float4 m2 = sh_m[SWZ(kbase + KSUB)];
            float la = __logf(a_hi);
            float m;
            if (la <= m1.x)      m = fmaf(a_hi, m1.x, -b_lo) - m1.y;
            else if (la >= m2.x) m = fmaf(a_hi, m2.x, -b_lo) - m2.y;
            else                 m = fmaf(a_hi, la - 1.0f, -b_lo);  // e^la==a_hi
            flag = (m >= -1e-2f);
            if (c == NCHUNK - 1 && q == NSUB - 1) flag = true;  // last-row exemption
        }

        // ---- exact gate scan, only on flagged slices (rare) ----
        bool  found = false;
        float ct    = INFINITY;
        if (flag) {
            float aa = a_run + ea;
            float bb = b_run + eb;
            float4 mc = sh_m[SWZ(kbase)];
            #pragma unroll
            for (int kk = 0; kk < KSUB; ++kk) {
                if (!found) {
                    aa = fmaf(wv[kk], mc.y, aa);
                    bb = fmaf(wv[kk], mc.z, bb);
                    float4 mn = sh_m[SWZ(kbase + kk + 1)];
                    // exact gate: z >= -1/e AND t <= s_next
                    if (fmaf(aa, mn.x, -bb) >= mn.y) {
                        float r = __fdividef(bb, aa);
                        float z = -__fdividef(__expf(r), aa);
                        bool valid = (aa > 0.0f) && (z >= -INV_E_F);
                        float t = r - lambertw0_dev(z);
                        if (valid && t >= mc.x) {    // causal lower bound
                            found = true; ct = t;    // first valid in slice
                        }
                    }
                    mc = mn;
                }
            }
        }

        // ---- per-neuron resolution: lowest-q found lane wins (min k) ----
        unsigned bal = __ballot_sync(FULL, found);
        unsigned gb  = bal & (0x11111111u << nl);
        int src = gb ? (int)(__ffs(gb) - 1) : l;
        float tw = __shfl_sync(FULL, ct, src);
        if (!done) {
            if (gb) {
                done = true;
                if (q == 0) out[b * NPOST + ng] = tw;
            } else {
                a_run += tot_a;
                b_run += tot_b;
            }
        }

        if (__all_sync(FULL, done)) break;   // warp-local early exit

        #pragma unroll
        for (int kk = 0; kk < KSUB; ++kk) wv[kk] = wn[kk];
    }

    if (!done && q == 0) out[b * NPOST + ng] = INFINITY;
}

// ---------------------------------------------------------------------------
extern "C" void kernel_launch(void* const* d_in, const int* in_sizes, int n_in,
                              void* d_out, int out_size)
{
    const float* spikes  = (const float*)d_in[0];
    const float* weights = (const float*)d_in[1];
    int sz = in_sizes[0];
    if (n_in >= 2 && in_sizes[0] > in_sizes[1]) {   // robustness to input order
        const float* t = spikes; spikes = weights; weights = t;
        sz = in_sizes[1];
    }
    int B = sz / NPRE;
    sort_kernel<<<B, 512>>>(spikes);
    scan_kernel<<<B * NGRP, NTHR>>>(weights, (float*)d_out);
}

// round 9
// speedup vs baseline: 1.4837x; 1.0089x over previous
#include <cuda_runtime.h>
#include <math.h>

#define NPRE   1024
#define NPOST  256
#define MAXB   128

// scan kernel geometry: warp = 8 slices x 4 lanes; each lane owns 2 neurons
#define CH     64                 // k-chunk length
#define NSUB   8                  // slices per chunk
#define KSUB   (CH / NSUB)        // 8 k per slice
#define NTHR   256                // 8 warps
#define NT     64                 // neurons per block (8 per warp x 8 warps)
#define NGRP   (NPOST / NT)       // 4 neuron groups per batch
#define NCHUNK (NPRE / CH)        // 16 chunks
#define CSTRIDE 72                // float4 stride per chunk (8 slices x 9)
#define FULL   0xffffffffu

#define INV_E_F  0.36787944117144233f
#define E_F      2.718281828459045f

// Scratch: packed per-k metadata (s, e^s, s*e^s, idx-bits), one row per batch.
__device__ float4 g_m4[MAXB * NPRE];

// ---------------------------------------------------------------------------
// Kernel 1: stable ascending sort of each batch row (matches jnp.argsort).
// (verified since R4) Emits packed float4 metadata.
// ---------------------------------------------------------------------------
__global__ void __launch_bounds__(512) sort_kernel(const float* __restrict__ spikes)
{
    __shared__ unsigned long long keys[NPRE];
    const int b   = blockIdx.x;
    const int tid = threadIdx.x;

    for (int i = tid; i < NPRE; i += 512) {
        float v = spikes[b * NPRE + i];
        unsigned int bits = __float_as_uint(v);
        bits = (bits & 0x80000000u) ? ~bits : (bits | 0x80000000u);
        keys[i] = ((unsigned long long)bits << 32) | (unsigned int)i;
    }
    __syncthreads();

    for (int k = 2; k <= NPRE; k <<= 1) {
        for (int j = k >> 1; j >= 32; j >>= 1) {
            #pragma unroll
            for (int rep = 0; rep < NPRE / 512; ++rep) {
                int i = tid + rep * 512;
                int ixj = i ^ j;
                if (ixj > i) {
                    unsigned long long A = keys[i];
                    unsigned long long C = keys[ixj];
                    bool up = ((i & k) == 0);
                    if ((A > C) == up) { keys[i] = C; keys[ixj] = A; }
                }
            }
            __syncthreads();
        }
        unsigned long long v0 = keys[tid];
        unsigned long long v1 = keys[tid + 512];
        const bool up0 = ((tid & k) == 0);
        const bool up1 = (((tid + 512) & k) == 0);
        #pragma unroll
        for (int j = 16; j >= 1; j >>= 1) {
            if (j < k) {
                bool lower = ((tid & j) == 0);
                unsigned long long p0 = __shfl_xor_sync(FULL, v0, j);
                unsigned long long p1 = __shfl_xor_sync(FULL, v1, j);
                bool km0 = (lower == up0);
                bool km1 = (lower == up1);
                unsigned long long mn0 = (v0 < p0) ? v0 : p0;
                unsigned long long mx0 = (v0 < p0) ? p0 : v0;
                unsigned long long mn1 = (v1 < p1) ? v1 : p1;
                unsigned long long mx1 = (v1 < p1) ? p1 : v1;
                v0 = km0 ? mn0 : mx0;
                v1 = km1 ? mn1 : mx1;
            }
        }
        keys[tid]       = v0;
        keys[tid + 512] = v1;
        __syncthreads();
    }

    for (int i = tid; i < NPRE; i += 512) {
        unsigned long long kk = keys[i];
        unsigned int hi = (unsigned int)(kk >> 32);
        unsigned int bits = (hi & 0x80000000u) ? (hi ^ 0x80000000u) : ~hi;
        float s = __uint_as_float(bits);
        float e = expf(s);
        g_m4[b * NPRE + i] =
            make_float4(s, e, s * e, __int_as_float((int)(kk & 0xFFFFFFFFu)));
    }
}

// ---------------------------------------------------------------------------
// Lambert W0 on [-1/e, 0): same clip/init/Halley form as the reference.
// ---------------------------------------------------------------------------
__device__ __forceinline__ float lambertw0_dev(float z)
{
    float zc = fminf(fmaxf(z, -INV_E_F + 1e-8f), -1e-30f);
    float w;
    if (zc < -0.2f)
        w = -1.0f + sqrtf(2.0f * fmaf(E_F, zc, 1.0f));
    else
        w = zc * (1.0f - zc);
    #pragma unroll
    for (int it = 0; it < 6; ++it) {
        float ew  = __expf(w);
        float f   = fmaf(w, ew, -zc);
        float wp1 = w + 1.0f;
        float denom = fmaf(2.0f * ew * wp1, wp1, -(w + 2.0f) * f);
        w = w - __fdividef(f * 2.0f * wp1, denom);
    }
    return w;
}

// ---------------------------------------------------------------------------
// Kernel 2: warp-autonomous chunked causal scan.
//   Padded stride-9 metadata layout: chunk c slice q at [c*72 + q*9 + kk],
//   slot 8 duplicates the successor element -> contiguous per-slice loads
//   with immediate offsets, conflict-free across q ((9q+kk) mod 8 distinct).
//   Each lane owns slice q of TWO adjacent neurons (float2 weight gathers).
//   Per chunk: slice totals -> shfl scan -> joint concavity prune (sound
//   upper bound; verified R4/R7/R8) -> exact gate scan + Lambert only on
//   flagged slices -> ballot min-k resolution. Warp exits when its 8
//   neurons are done. Single __syncthreads in the whole kernel.
// ---------------------------------------------------------------------------
__global__ void __launch_bounds__(NTHR) scan_kernel(const float* __restrict__ Wmat,
                                                    float* __restrict__ out)
{
    __shared__ float4 sh_m[NCHUNK * CSTRIDE];

    const int b    = blockIdx.x / NGRP;
    const int grp  = blockIdx.x % NGRP;
    const int tid  = threadIdx.x;
    const int wrp  = tid >> 5;
    const int l    = tid & 31;
    const int q    = l >> 2;            // slice 0..7
    const int nl   = l & 3;             // neuron-pair-in-warp 0..3
    const int n0   = grp * NT + wrp * 8 + nl * 2;   // first of 2 neurons
    const int cn   = n0 >> 1;           // float2 column in W
    const int base = b * NPRE;
    const float2* __restrict__ W2 = (const float2*)Wmat;

    // ---- stage metadata once into padded layout ----
    for (int i = tid; i < NPRE; i += NTHR) {
        float4 m = g_m4[base + i];
        int c = i >> 6, qq = (i >> 3) & 7, kk = i & 7;
        sh_m[c * CSTRIDE + qq * 9 + kk] = m;
        if (kk == 0 && i > 0) {          // duplicate into predecessor's slot 8
            int ip = i - 8;
            sh_m[(ip >> 6) * CSTRIDE + ((ip >> 3) & 7) * 9 + 8] = m;
        }
    }
    if (tid == 0)                        // sentinel successor of k=1023
        sh_m[15 * CSTRIDE + 7 * 9 + 8] = make_float4(INFINITY, INFINITY, 0.0f, 0.0f);
    __syncthreads();

    const float4* mp = sh_m + q * 9;     // this lane's slice, chunk 0

    // ---- prologue: chunk-0 weights (2 neurons per lane) ----
    float2 wv[KSUB];
    #pragma unroll
    for (int kk = 0; kk < KSUB; ++kk) {
        int row = __float_as_int(mp[kk].w);
        wv[kk] = __ldg(&W2[row * (NPOST >> 1) + cn]);
    }

    bool  done0 = false, done1 = false;
    float arun0 = 0.0f, brun0 = 0.0f, arun1 = 0.0f, brun1 = 0.0f;

    for (int c = 0; c < NCHUNK; ++c) {
        const bool act = !(done0 && done1);

        // ---- slice totals (contiguous conflict-free LDS.128) ----
        float pa0 = 0.0f, pb0 = 0.0f, pa1 = 0.0f, pb1 = 0.0f;
        if (act) {
            #pragma unroll
            for (int kk = 0; kk < KSUB; ++kk) {
                float4 m = mp[kk];
                pa0 = fmaf(wv[kk].x, m.y, pa0);
                pb0 = fmaf(wv[kk].x, m.z, pb0);
                pa1 = fmaf(wv[kk].y, m.y, pa1);
                pb1 = fmaf(wv[kk].y, m.z, pb1);
            }
        }
        // ---- prefetch next chunk weights ----
        float2 wn[KSUB];
        if (act && c + 1 < NCHUNK) {
            #pragma unroll
            for (int kk = 0; kk < KSUB; ++kk) {
                int row = __float_as_int(mp[CSTRIDE + kk].w);
                wn[kk] = __ldg(&W2[row * (NPOST >> 1) + cn]);
            }
        }

        // ---- segmented inclusive scan over q (stride-4 lanes) ----
        float ia0 = pa0, ib0 = pb0, ia1 = pa1, ib1 = pb1, t;
        t = __shfl_up_sync(FULL, ia0, 4);  if (q >= 1) ia0 += t;
        t = __shfl_up_sync(FULL, ib0, 4);  if (q >= 1) ib0 += t;
        t = __shfl_up_sync(FULL, ia1, 4);  if (q >= 1) ia1 += t;
        t = __shfl_up_sync(FULL, ib1, 4);  if (q >= 1) ib1 += t;
        t = __shfl_up_sync(FULL, ia0, 8);  if (q >= 2) ia0 += t;
        t = __shfl_up_sync(FULL, ib0, 8);  if (q >= 2) ib0 += t;
        t = __shfl_up_sync(FULL, ia1, 8);  if (q >= 2) ia1 += t;
        t = __shfl_up_sync(FULL, ib1, 8);  if (q >= 2) ib1 += t;
        t = __shfl_up_sync(FULL, ia0, 16); if (q >= 4) ia0 += t;
        t = __shfl_up_sync(FULL, ib0, 16); if (q >= 4) ib0 += t;
        t = __shfl_up_sync(FULL, ia1, 16); if (q >= 4) ia1 += t;
        t = __shfl_up_sync(FULL, ib1, 16); if (q >= 4) ib1 += t;
        float ea0 = ia0 - pa0, eb0 = ib0 - pb0;     // exclusive prefix, no shfl
        float ea1 = ia1 - pa1, eb1 = ib1 - pb1;
        float tota0 = __shfl_sync(FULL, ia0, 28 + nl);
        float totb0 = __shfl_sync(FULL, ib0, 28 + nl);
        float tota1 = __shfl_sync(FULL, ia1, 28 + nl);
        float totb1 = __shfl_sync(FULL, ib1, 28 + nl);

        // ---- joint concavity prune (sound upper bound for both neurons) ----
        bool flag = false;
        if (act) {
            float a_hi = fmaxf(arun0 + ea0 + pa0, arun1 + ea1 + pa1);
            float b_lo = fminf(brun0 + eb0, brun1 + eb1);
            float4 m1 = mp[1];
            float4 m2 = mp[8];
            float la = __logf(a_hi);
            float m;
            if (la <= m1.x)      m = fmaf(a_hi, m1.x, -b_lo) - m1.y;
            else if (la >= m2.x) m = fmaf(a_hi, m2.x, -b_lo) - m2.y;
            else                 m = fmaf(a_hi, la - 1.0f, -b_lo);  // e^la==a_hi
            flag = (m >= -1e-2f);
            if (c == NCHUNK - 1 && q == NSUB - 1) flag = true;  // last-row exemption
        }

        // ---- exact gate scans, flagged slices only (rare) ----
        bool  found0 = false, found1 = false;
        float ct0 = INFINITY, ct1 = INFINITY;
        if (flag && !done0) {
            float aa = arun0 + ea0, bb = brun0 + eb0;
            float4 mc = mp[0];
            #pragma unroll
            for (int kk = 0; kk < KSUB; ++kk) {
                if (!found0) {
                    aa = fmaf(wv[kk].x, mc.y, aa);
                    bb = fmaf(wv[kk].x, mc.z, bb);
                    float4 mn = mp[kk + 1];
                    if (fmaf(aa, mn.x, -bb) >= mn.y) {   // z>=-1/e AND t<=s_next
                        float r = __fdividef(bb, aa);
                        float z = -__fdividef(__expf(r), aa);
                        bool valid = (aa > 0.0f) && (z >= -INV_E_F);
                        float tt = r - lambertw0_dev(z);
                        if (valid && tt >= mc.x) { found0 = true; ct0 = tt; }
                    }
                    mc = mn;
                }
            }
        }
        if (flag && !done1) {
            float aa = arun1 + ea1, bb = brun1 + eb1;
            float4 mc = mp[0];
            #pragma unroll
            for (int kk = 0; kk < KSUB; ++kk) {
                if (!found1) {
                    aa = fmaf(wv[kk].y, mc.y, aa);
                    bb = fmaf(wv[kk].y, mc.z, bb);
                    float4 mn = mp[kk + 1];
                    if (fmaf(aa, mn.x, -bb) >= mn.y) {
                        float r = __fdividef(bb, aa);
                        float z = -__fdividef(__expf(r), aa);
                        bool valid = (aa > 0.0f) && (z >= -INV_E_F);
                        float tt = r - lambertw0_dev(z);
                        if (valid && tt >= mc.x) { found1 = true; ct1 = tt; }
                    }
                    mc = mn;
                }
            }
        }

        // ---- per-neuron resolution: lowest-q found lane wins (min k) ----
        unsigned bal0 = __ballot_sync(FULL, found0);
        unsigned bal1 = __ballot_sync(FULL, found1);
        if (bal0 | bal1) {
            unsigned gb0 = bal0 & (0x11111111u << nl);
            unsigned gb1 = bal1 & (0x11111111u << nl);
            int s0 = gb0 ? (int)(__ffs(gb0) - 1) : l;
            int s1 = gb1 ? (int)(__ffs(gb1) - 1) : l;
            float tw0 = __shfl_sync(FULL, ct0, s0);
            float tw1 = __shfl_sync(FULL, ct1, s1);
            if (!done0) {
                if (gb0) { done0 = true; if (q == 0) out[b * NPOST + n0] = tw0; }
                else     { arun0 += tota0; brun0 += totb0; }
            }
            if (!done1) {
                if (gb1) { done1 = true; if (q == 0) out[b * NPOST + n0 + 1] = tw1; }
                else     { arun1 += tota1; brun1 += totb1; }
            }
        } else {
            if (!done0) { arun0 += tota0; brun0 += totb0; }
            if (!done1) { arun1 += tota1; brun1 += totb1; }
        }

        if (__all_sync(FULL, done0 && done1)) break;   // warp-local early exit

        #pragma unroll
        for (int kk = 0; kk < KSUB; ++kk) wv[kk] = wn[kk];
        mp += CSTRIDE;
    }

    if (q == 0) {
        if (!done0) out[b * NPOST + n0]     = INFINITY;
        if (!done1) out[b * NPOST + n0 + 1] = INFINITY;
    }
}

// ---------------------------------------------------------------------------
extern "C" void kernel_launch(void* const* d_in, const int* in_sizes, int n_in,
                              void* d_out, int out_size)
{
    const float* spikes  = (const float*)d_in[0];
    const float* weights = (const float*)d_in[1];
    int sz = in_sizes[0];
    if (n_in >= 2 && in_sizes[0] > in_sizes[1]) {   // robustness to input order
        const float* t = spikes; spikes = weights; weights = t;
        sz = in_sizes[1];
    }
    int B = sz / NPRE;
    sort_kernel<<<B, 512>>>(spikes);
    scan_kernel<<<B * NGRP, NTHR>>>(weights, (float*)d_out);
}

// round 10
// speedup vs baseline: 2.2263x; 1.5006x over previous
#include <cuda_runtime.h>
#include <math.h>

#define NPRE   1024
#define NPOST  256
#define MAXB   128

// scan kernel geometry: warp = 8 slices x 4 lanes; each lane owns 2 neurons
#define CH     64                 // k-chunk length
#define NSUB   8                  // slices per chunk
#define KSUB   (CH / NSUB)        // 8 k per slice
#define NTHR   256                // 8 warps
#define NT     64                 // neurons per block (8 per warp x 8 warps)
#define NGRP   (NPOST / NT)       // 4 neuron groups per batch
#define NCHUNK (NPRE / CH)        // 16 chunks
#define CSTRIDE 72                // float4 stride per chunk (8 slices x 9)
#define FULL   0xffffffffu

#define INV_E_F  0.36787944117144233f
#define E_F      2.718281828459045f

// Scratch: packed per-k metadata (s, e^s, s*e^s, idx-bits), one row per batch.
__device__ float4 g_m4[MAXB * NPRE];

// ---------------------------------------------------------------------------
// Kernel 1: stable ascending sort of each batch row (matches jnp.argsort).
// (verified since R4) Emits packed float4 metadata.
// ---------------------------------------------------------------------------
__global__ void __launch_bounds__(512) sort_kernel(const float* __restrict__ spikes)
{
    __shared__ unsigned long long keys[NPRE];
    const int b   = blockIdx.x;
    const int tid = threadIdx.x;

    for (int i = tid; i < NPRE; i += 512) {
        float v = spikes[b * NPRE + i];
        unsigned int bits = __float_as_uint(v);
        bits = (bits & 0x80000000u) ? ~bits : (bits | 0x80000000u);
        keys[i] = ((unsigned long long)bits << 32) | (unsigned int)i;
    }
    __syncthreads();

    for (int k = 2; k <= NPRE; k <<= 1) {
        for (int j = k >> 1; j >= 32; j >>= 1) {
            #pragma unroll
            for (int rep = 0; rep < NPRE / 512; ++rep) {
                int i = tid + rep * 512;
                int ixj = i ^ j;
                if (ixj > i) {
                    unsigned long long A = keys[i];
                    unsigned long long C = keys[ixj];
                    bool up = ((i & k) == 0);
                    if ((A > C) == up) { keys[i] = C; keys[ixj] = A; }
                }
            }
            __syncthreads();
        }
        unsigned long long v0 = keys[tid];
        unsigned long long v1 = keys[tid + 512];
        const bool up0 = ((tid & k) == 0);
        const bool up1 = (((tid + 512) & k) == 0);
        #pragma unroll
        for (int j = 16; j >= 1; j >>= 1) {
            if (j < k) {
                bool lower = ((tid & j) == 0);
                unsigned long long p0 = __shfl_xor_sync(FULL, v0, j);
                unsigned long long p1 = __shfl_xor_sync(FULL, v1, j);
                bool km0 = (lower == up0);
                bool km1 = (lower == up1);
                unsigned long long mn0 = (v0 < p0) ? v0 : p0;
                unsigned long long mx0 = (v0 < p0) ? p0 : v0;
                unsigned long long mn1 = (v1 < p1) ? v1 : p1;
                unsigned long long mx1 = (v1 < p1) ? p1 : v1;
                v0 = km0 ? mn0 : mx0;
                v1 = km1 ? mn1 : mx1;
            }
        }
        keys[tid]       = v0;
        keys[tid + 512] = v1;
        __syncthreads();
    }

    for (int i = tid; i < NPRE; i += 512) {
        unsigned long long kk = keys[i];
        unsigned int hi = (unsigned int)(kk >> 32);
        unsigned int bits = (hi & 0x80000000u) ? (hi ^ 0x80000000u) : ~hi;
        float s = __uint_as_float(bits);
        float e = expf(s);
        g_m4[b * NPRE + i] =
            make_float4(s, e, s * e, __int_as_float((int)(kk & 0xFFFFFFFFu)));
    }
}

// ---------------------------------------------------------------------------
// Lambert W0 on [-1/e, 0): same clip/init/Halley form as the reference.
// ---------------------------------------------------------------------------
__device__ __forceinline__ float lambertw0_dev(float z)
{
    float zc = fminf(fmaxf(z, -INV_E_F + 1e-8f), -1e-30f);
    float w;
    if (zc < -0.2f)
        w = -1.0f + sqrtf(2.0f * fmaf(E_F, zc, 1.0f));
    else
        w = zc * (1.0f - zc);
    #pragma unroll
    for (int it = 0; it < 6; ++it) {
        float ew  = __expf(w);
        float f   = fmaf(w, ew, -zc);
        float wp1 = w + 1.0f;
        float denom = fmaf(2.0f * ew * wp1, wp1, -(w + 2.0f) * f);
        w = w - __fdividef(f * 2.0f * wp1, denom);
    }
    return w;
}

// ---------------------------------------------------------------------------
// Kernel 2: warp-autonomous chunked causal scan, deferred-Lambert resolution.
//   (layout + prune verified R8/R9) Per chunk: slice totals -> shfl scan ->
//   concavity prune -> CHEAP gate-pass scan (FMA/SEL only, records first
//   pass k and its (a,b)) -> ballot min-k -> ONE Lambert on the winning
//   lane -> validity check; rare failure falls back to the verified R9
//   per-lane full scan. Single __syncthreads in the whole kernel.
// ---------------------------------------------------------------------------
__global__ void __launch_bounds__(NTHR) scan_kernel(const float* __restrict__ Wmat,
                                                    float* __restrict__ out)
{
    __shared__ float4 sh_m[NCHUNK * CSTRIDE];

    const int b    = blockIdx.x / NGRP;
    const int grp  = blockIdx.x % NGRP;
    const int tid  = threadIdx.x;
    const int wrp  = tid >> 5;
    const int l    = tid & 31;
    const int q    = l >> 2;            // slice 0..7
    const int nl   = l & 3;             // neuron-pair-in-warp 0..3
    const int n0   = grp * NT + wrp * 8 + nl * 2;   // first of 2 neurons
    const int cn   = n0 >> 1;           // float2 column in W
    const int base = b * NPRE;
    const float2* __restrict__ W2 = (const float2*)Wmat;

    // ---- stage metadata once into padded layout ----
    for (int i = tid; i < NPRE; i += NTHR) {
        float4 m = g_m4[base + i];
        int c = i >> 6, qq = (i >> 3) & 7, kk = i & 7;
        sh_m[c * CSTRIDE + qq * 9 + kk] = m;
        if (kk == 0 && i > 0) {          // duplicate into predecessor's slot 8
            int ip = i - 8;
            sh_m[(ip >> 6) * CSTRIDE + ((ip >> 3) & 7) * 9 + 8] = m;
        }
    }
    if (tid == 0)                        // sentinel successor of k=1023
        sh_m[15 * CSTRIDE + 7 * 9 + 8] = make_float4(INFINITY, INFINITY, 0.0f, 0.0f);
    __syncthreads();

    const float4* mp = sh_m + q * 9;     // this lane's slice, chunk 0

    // ---- prologue: chunk-0 weights (2 neurons per lane) ----
    float2 wv[KSUB];
    #pragma unroll
    for (int kk = 0; kk < KSUB; ++kk) {
        int row = __float_as_int(mp[kk].w);
        wv[kk] = __ldg(&W2[row * (NPOST >> 1) + cn]);
    }

    bool  done0 = false, done1 = false;
    float arun0 = 0.0f, brun0 = 0.0f, arun1 = 0.0f, brun1 = 0.0f;

    for (int c = 0; c < NCHUNK; ++c) {
        const bool act = !(done0 && done1);

        // ---- slice totals (contiguous conflict-free LDS.128) ----
        float pa0 = 0.0f, pb0 = 0.0f, pa1 = 0.0f, pb1 = 0.0f;
        if (act) {
            #pragma unroll
            for (int kk = 0; kk < KSUB; ++kk) {
                float4 m = mp[kk];
                pa0 = fmaf(wv[kk].x, m.y, pa0);
                pb0 = fmaf(wv[kk].x, m.z, pb0);
                pa1 = fmaf(wv[kk].y, m.y, pa1);
                pb1 = fmaf(wv[kk].y, m.z, pb1);
            }
        }
        // ---- prefetch next chunk weights ----
        float2 wn[KSUB];
        if (act && c + 1 < NCHUNK) {
            #pragma unroll
            for (int kk = 0; kk < KSUB; ++kk) {
                int row = __float_as_int(mp[CSTRIDE + kk].w);
                wn[kk] = __ldg(&W2[row * (NPOST >> 1) + cn]);
            }
        }

        // ---- segmented inclusive scan over q (stride-4 lanes) ----
        float ia0 = pa0, ib0 = pb0, ia1 = pa1, ib1 = pb1, t;
        t = __shfl_up_sync(FULL, ia0, 4);  if (q >= 1) ia0 += t;
        t = __shfl_up_sync(FULL, ib0, 4);  if (q >= 1) ib0 += t;
        t = __shfl_up_sync(FULL, ia1, 4);  if (q >= 1) ia1 += t;
        t = __shfl_up_sync(FULL, ib1, 4);  if (q >= 1) ib1 += t;
        t = __shfl_up_sync(FULL, ia0, 8);  if (q >= 2) ia0 += t;
        t = __shfl_up_sync(FULL, ib0, 8);  if (q >= 2) ib0 += t;
        t = __shfl_up_sync(FULL, ia1, 8);  if (q >= 2) ia1 += t;
        t = __shfl_up_sync(FULL, ib1, 8);  if (q >= 2) ib1 += t;
        t = __shfl_up_sync(FULL, ia0, 16); if (q >= 4) ia0 += t;
        t = __shfl_up_sync(FULL, ib0, 16); if (q >= 4) ib0 += t;
        t = __shfl_up_sync(FULL, ia1, 16); if (q >= 4) ia1 += t;
        t = __shfl_up_sync(FULL, ib1, 16); if (q >= 4) ib1 += t;
        float ea0 = ia0 - pa0, eb0 = ib0 - pb0;     // exclusive prefix
        float ea1 = ia1 - pa1, eb1 = ib1 - pb1;
        float tota0 = __shfl_sync(FULL, ia0, 28 + nl);
        float totb0 = __shfl_sync(FULL, ib0, 28 + nl);
        float tota1 = __shfl_sync(FULL, ia1, 28 + nl);
        float totb1 = __shfl_sync(FULL, ib1, 28 + nl);

        // ---- joint concavity prune (sound upper bound; verified R4..R9) ----
        bool flag = false;
        if (act) {
            float a_hi = fmaxf(arun0 + ia0, arun1 + ia1);
            float b_lo = fminf(brun0 + eb0, brun1 + eb1);
            float4 m1 = mp[1];
            float4 m2 = mp[8];
            float la = __logf(a_hi);
            float m;
            if (la <= m1.x)      m = fmaf(a_hi, m1.x, -b_lo) - m1.y;
            else if (la >= m2.x) m = fmaf(a_hi, m2.x, -b_lo) - m2.y;
            else                 m = fmaf(a_hi, la - 1.0f, -b_lo);  // e^la==a_hi
            flag = (m >= -1e-2f);
            if (c == NCHUNK - 1 && q == NSUB - 1) flag = true;  // last-row exemption
        }

        // ---- cheap gate-pass scan (NO Lambert): first pass k + its (a,b) ----
        int   fk0 = 8, fk1 = 8;
        float ca0 = 0.0f, cb0 = 0.0f, ca1 = 0.0f, cb1 = 0.0f;
        if (flag) {
            if (!done0) {
                float aa = arun0 + ea0, bb = brun0 + eb0;
                float4 mc = mp[0];
                #pragma unroll
                for (int kk = 0; kk < KSUB; ++kk) {
                    aa = fmaf(wv[kk].x, mc.y, aa);
                    bb = fmaf(wv[kk].x, mc.z, bb);
                    float4 mn = mp[kk + 1];
                    if (fk0 == 8 && fmaf(aa, mn.x, -bb) >= mn.y) {
                        fk0 = kk; ca0 = aa; cb0 = bb;
                    }
                    mc = mn;
                }
            }
            if (!done1) {
                float aa = arun1 + ea1, bb = brun1 + eb1;
                float4 mc = mp[0];
                #pragma unroll
                for (int kk = 0; kk < KSUB; ++kk) {
                    aa = fmaf(wv[kk].y, mc.y, aa);
                    bb = fmaf(wv[kk].y, mc.z, bb);
                    float4 mn = mp[kk + 1];
                    if (fk1 == 8 && fmaf(aa, mn.x, -bb) >= mn.y) {
                        fk1 = kk; ca1 = aa; cb1 = bb;
                    }
                    mc = mn;
                }
            }
        }

        // ---- min-k resolution: ONE Lambert on the winning lane ----
        unsigned bal0 = __ballot_sync(FULL, fk0 < 8);
        unsigned bal1 = __ballot_sync(FULL, fk1 < 8);
        bool fired0 = false, fired1 = false;
        float t0 = INFINITY, t1 = INFINITY;
        if (bal0 | bal1) {                              // warp-uniform guard
            unsigned gb0 = bal0 & (0x11111111u << nl);
            unsigned gb1 = bal1 & (0x11111111u << nl);
            int src0 = gb0 ? (int)(__ffs(gb0) - 1) : l;
            int src1 = gb1 ? (int)(__ffs(gb1) - 1) : l;
            int ok0 = 0, ok1 = 0;
            if (gb0 && l == src0) {                     // winner eval neuron 0
                float r = __fdividef(cb0, ca0);
                float z = -__fdividef(__expf(r), ca0);
                float tt = r - lambertw0_dev(z);
                ok0 = (ca0 > 0.0f) && (z >= -INV_E_F) && (tt >= mp[fk0].x);
                t0 = tt;
            }
            if (gb1 && l == src1) {                     // winner eval neuron 1
                float r = __fdividef(cb1, ca1);
                float z = -__fdividef(__expf(r), ca1);
                float tt = r - lambertw0_dev(z);
                ok1 = (ca1 > 0.0f) && (z >= -INV_E_F) && (tt >= mp[fk1].x);
                t1 = tt;
            }
            ok0 = __shfl_sync(FULL, ok0, src0);  t0 = __shfl_sync(FULL, t0, src0);
            ok1 = __shfl_sync(FULL, ok1, src1);  t1 = __shfl_sync(FULL, t1, src1);
            fired0 = gb0 && ok0 && !done0;
            fired1 = gb1 && ok1 && !done1;

            // ---- rare fallback: winner invalid -> verified full per-lane scan
            bool nf0 = gb0 && !ok0 && !done0;
            bool nf1 = gb1 && !ok1 && !done1;
            if (__ballot_sync(FULL, nf0 || nf1)) {
                bool  f0 = false, f1 = false;
                float c0 = INFINITY, c1 = INFINITY;
                if (nf0 && flag) {
                    float aa = arun0 + ea0, bb = brun0 + eb0;
                    float4 mc = mp[0];
                    #pragma unroll
                    for (int kk = 0; kk < KSUB; ++kk) {
                        if (!f0) {
                            aa = fmaf(wv[kk].x, mc.y, aa);
                            bb = fmaf(wv[kk].x, mc.z, bb);
                            float4 mn = mp[kk + 1];
                            if (fmaf(aa, mn.x, -bb) >= mn.y) {
                                float r = __fdividef(bb, aa);
                                float z = -__fdividef(__expf(r), aa);
                                bool valid = (aa > 0.0f) && (z >= -INV_E_F);
                                float tt = r - lambertw0_dev(z);
                                if (valid && tt >= mc.x) { f0 = true; c0 = tt; }
                            }
                            mc = mn;
                        }
                    }
                }
                if (nf1 && flag) {
                    float aa = arun1 + ea1, bb = brun1 + eb1;
                    float4 mc = mp[0];
                    #pragma unroll
                    for (int kk = 0; kk < KSUB; ++kk) {
                        if (!f1) {
                            aa = fmaf(wv[kk].y, mc.y, aa);
                            bb = fmaf(wv[kk].y, mc.z, bb);
                            float4 mn = mp[kk + 1];
                            if (fmaf(aa, mn.x, -bb) >= mn.y) {
                                float r = __fdividef(bb, aa);
                                float z = -__fdividef(__expf(r), aa);
                                bool valid = (aa > 0.0f) && (z >= -INV_E_F);
                                float tt = r - lambertw0_dev(z);
                                if (valid && tt >= mc.x) { f1 = true; c1 = tt; }
                            }
                            mc = mn;
                        }
                    }
                }
                unsigned fb0 = __ballot_sync(FULL, f0) & (0x11111111u << nl);
                unsigned fb1 = __ballot_sync(FULL, f1) & (0x11111111u << nl);
                int fs0 = fb0 ? (int)(__ffs(fb0) - 1) : l;
                int fs1 = fb1 ? (int)(__ffs(fb1) - 1) : l;
                float ft0 = __shfl_sync(FULL, c0, fs0);
                float ft1 = __shfl_sync(FULL, c1, fs1);
                if (nf0 && fb0) { fired0 = true; t0 = ft0; }
                if (nf1 && fb1) { fired1 = true; t1 = ft1; }
            }
        }

        // ---- commit chunk results ----
        if (!done0) {
            if (fired0) { done0 = true; if (q == 0) out[b * NPOST + n0] = t0; }
            else        { arun0 += tota0; brun0 += totb0; }
        }
        if (!done1) {
            if (fired1) { done1 = true; if (q == 0) out[b * NPOST + n0 + 1] = t1; }
            else        { arun1 += tota1; brun1 += totb1; }
        }

        if (__all_sync(FULL, done0 && done1)) break;   // warp-local early exit

        #pragma unroll
        for (int kk = 0; kk < KSUB; ++kk) wv[kk] = wn[kk];
        mp += CSTRIDE;
    }

    if (q == 0) {
        if (!done0) out[b * NPOST + n0]     = INFINITY;
        if (!done1) out[b * NPOST + n0 + 1] = INFINITY;
    }
}

// ---------------------------------------------------------------------------
extern "C" void kernel_launch(void* const* d_in, const int* in_sizes, int n_in,
                              void* d_out, int out_size)
{
    const float* spikes  = (const float*)d_in[0];
    const float* weights = (const float*)d_in[1];
    int sz = in_sizes[0];
    if (n_in >= 2 && in_sizes[0] > in_sizes[1]) {   // robustness to input order
        const float* t = spikes; spikes = weights; weights = t;
        sz = in_sizes[1];
    }
    int B = sz / NPRE;
    sort_kernel<<<B, 512>>>(spikes);
    scan_kernel<<<B * NGRP, NTHR>>>(weights, (float*)d_out);
}